// round 1
// baseline (speedup 1.0000x reference)
#include <cuda_runtime.h>
#include <math.h>

// Problem constants
#define BB 4
#define CH 4096     // HID
#define SS 2048     // S
#define NH 32       // heads
#define HD 128      // head dim

#define BHS 33554432  // BB*CH*SS elements

// Scratch (allocation-free rule: __device__ globals)
__device__ float g_q[BHS];
__device__ float g_attn[BHS];
__device__ float g_kfb[BHS];   // fallback K dest if out_size doesn't cover 3 tensors
__device__ float g_vfb[BHS];   // fallback V dest

// ---------------------------------------------------------------------------
// GEMM: Y[b] (M x N) = W (M x K, row-major) @ X[b] (K x N, row-major) + bias
// Tiles: 128x128x16, 256 threads, 8x8 per-thread micro-tile.
// ---------------------------------------------------------------------------
#define TM 128
#define TN 128
#define TK 16
#define APAD 20   // padded row stride for A tile (16B-aligned, reduces conflicts)

__global__ __launch_bounds__(256, 1) void gemm_bias_kernel(
    const float* __restrict__ W, const float* __restrict__ X,
    const float* __restrict__ bias, float* __restrict__ Y,
    int M, int N, int K)
{
    __shared__ float As[TM * APAD];   // As[m][k], row stride APAD
    __shared__ float Bs[TK * TN];     // Bs[k][n]

    const int t  = threadIdx.x;
    const int m0 = blockIdx.y * TM;
    const int n0 = blockIdx.x * TN;

    const float* Xb = X + (size_t)blockIdx.z * (size_t)K * (size_t)N;
    float*       Yb = Y + (size_t)blockIdx.z * (size_t)M * (size_t)N;

    const int tm = (t >> 4) << 3;   // 0..120
    const int tn = (t & 15) << 3;   // 0..120

    float acc[8][8];
#pragma unroll
    for (int i = 0; i < 8; i++)
#pragma unroll
        for (int j = 0; j < 8; j++) acc[i][j] = 0.0f;

    for (int k0 = 0; k0 < K; k0 += TK) {
        // Load A tile: 128 rows x 16 cols = 512 float4, 2 per thread
#pragma unroll
        for (int i = 0; i < 2; i++) {
            int idx = i * 256 + t;
            int m   = idx >> 2;            // 0..127
            int c   = (idx & 3) << 2;      // 0,4,8,12
            float4 va = *(const float4*)(&W[(size_t)(m0 + m) * K + k0 + c]);
            *(float4*)(&As[m * APAD + c]) = va;
        }
        // Load B tile: 16 rows x 128 cols = 512 float4, 2 per thread
#pragma unroll
        for (int i = 0; i < 2; i++) {
            int idx = i * 256 + t;
            int r   = idx >> 5;            // 0..15
            int c   = (idx & 31) << 2;     // 0..124
            float4 vb = *(const float4*)(&Xb[(size_t)(k0 + r) * N + n0 + c]);
            *(float4*)(&Bs[r * TN + c]) = vb;
        }
        __syncthreads();

#pragma unroll 4
        for (int k = 0; k < TK; k++) {
            float a[8], b[8];
#pragma unroll
            for (int i = 0; i < 8; i++) a[i] = As[(tm + i) * APAD + k];
            float4 b0 = *(const float4*)(&Bs[k * TN + tn]);
            float4 b1 = *(const float4*)(&Bs[k * TN + tn + 4]);
            b[0] = b0.x; b[1] = b0.y; b[2] = b0.z; b[3] = b0.w;
            b[4] = b1.x; b[5] = b1.y; b[6] = b1.z; b[7] = b1.w;
#pragma unroll
            for (int i = 0; i < 8; i++)
#pragma unroll
                for (int j = 0; j < 8; j++) acc[i][j] += a[i] * b[j];
        }
        __syncthreads();
    }

#pragma unroll
    for (int i = 0; i < 8; i++) {
        float bv = bias[m0 + tm + i];
        float4 o0, o1;
        o0.x = acc[i][0] + bv; o0.y = acc[i][1] + bv;
        o0.z = acc[i][2] + bv; o0.w = acc[i][3] + bv;
        o1.x = acc[i][4] + bv; o1.y = acc[i][5] + bv;
        o1.z = acc[i][6] + bv; o1.w = acc[i][7] + bv;
        float* yp = &Yb[(size_t)(m0 + tm + i) * N + n0 + tn];
        *(float4*)(yp)     = o0;
        *(float4*)(yp + 4) = o1;
    }
}

// ---------------------------------------------------------------------------
// Attention per (b,h): scores = Q K^T / sqrt(S) (128x128, causal),
// softmax rows, attn = P @ V (128 x 2048). One CTA per head. 256 threads.
// SMEM: p[128][128] + two 16x132 staging buffers (dynamic, 82432 B).
// ---------------------------------------------------------------------------
#define VPAD 132

__global__ __launch_bounds__(256, 1) void attn_kernel(
    const float* __restrict__ Q, const float* __restrict__ Kt,
    const float* __restrict__ V, float* __restrict__ O)
{
    extern __shared__ float sm[];
    float* p_s  = sm;                        // 128*128
    float* bufA = sm + 128 * 128;            // 16*VPAD
    float* bufB = bufA + 16 * VPAD;          // 16*VPAD

    const int bh = blockIdx.x;               // 0..127 == b*32 + h
    const size_t base = (size_t)bh * HD * SS;
    const float* q = Q  + base;
    const float* k = Kt + base;
    const float* v = V  + base;
    float*       o = O  + base;

    const int t  = threadIdx.x;
    const int tm = (t >> 4) << 3;
    const int tn = (t & 15) << 3;

    // -------- Phase 1: scores = q k^T (contract over s) --------
    float acc[8][8];
#pragma unroll
    for (int i = 0; i < 8; i++)
#pragma unroll
        for (int j = 0; j < 8; j++) acc[i][j] = 0.0f;

    for (int s0 = 0; s0 < SS; s0 += 16) {
#pragma unroll
        for (int i = 0; i < 8; i++) {
            int idx = i * 256 + t;
            int d   = idx >> 4;      // 0..127
            int sk  = idx & 15;      // 0..15
            bufA[sk * VPAD + d] = q[(size_t)d * SS + s0 + sk];
            bufB[sk * VPAD + d] = k[(size_t)d * SS + s0 + sk];
        }
        __syncthreads();
#pragma unroll 4
        for (int sk = 0; sk < 16; sk++) {
            float a[8], b[8];
#pragma unroll
            for (int i = 0; i < 8; i++) a[i] = bufA[sk * VPAD + tm + i];
#pragma unroll
            for (int j = 0; j < 8; j++) b[j] = bufB[sk * VPAD + tn + j];
#pragma unroll
            for (int i = 0; i < 8; i++)
#pragma unroll
                for (int j = 0; j < 8; j++) acc[i][j] += a[i] * b[j];
        }
        __syncthreads();
    }

    const float scale = rsqrtf((float)SS);
#pragma unroll
    for (int i = 0; i < 8; i++)
#pragma unroll
        for (int j = 0; j < 8; j++) {
            int r = tm + i, c = tn + j;
            p_s[r * 128 + c] = (c <= r) ? acc[i][j] * scale : 0.0f;
        }
    __syncthreads();

    // -------- Softmax (causal rows; masked cols stay 0) --------
    if (t < 128) {
        float* row = &p_s[t * 128];
        float mx = -3.0e38f;
        for (int e = 0; e <= t; e++) mx = fmaxf(mx, row[e]);
        float sum = 0.0f;
        for (int e = 0; e <= t; e++) {
            float ex = __expf(row[e] - mx);
            row[e] = ex;
            sum += ex;
        }
        float inv = 1.0f / sum;
        for (int e = 0; e <= t; e++) row[e] *= inv;
    }
    __syncthreads();

    // -------- Phase 2: attn = P @ V --------
    for (int n0 = 0; n0 < SS; n0 += 128) {
        float acc2[8][8];
#pragma unroll
        for (int i = 0; i < 8; i++)
#pragma unroll
            for (int j = 0; j < 8; j++) acc2[i][j] = 0.0f;

        for (int e0 = 0; e0 < HD; e0 += 16) {
#pragma unroll
            for (int i = 0; i < 8; i++) {
                int idx = i * 256 + t;
                int ek  = idx >> 7;       // 0..15
                int col = idx & 127;      // 0..127
                bufA[ek * VPAD + col] = v[(size_t)(e0 + ek) * SS + n0 + col];
            }
            __syncthreads();
#pragma unroll 4
            for (int ek = 0; ek < 16; ek++) {
                float a[8], b[8];
#pragma unroll
                for (int i = 0; i < 8; i++) a[i] = p_s[(tm + i) * 128 + e0 + ek];
#pragma unroll
                for (int j = 0; j < 8; j++) b[j] = bufA[ek * VPAD + tn + j];
#pragma unroll
                for (int i = 0; i < 8; i++)
#pragma unroll
                    for (int j = 0; j < 8; j++) acc2[i][j] += a[i] * b[j];
            }
            __syncthreads();
        }

#pragma unroll
        for (int i = 0; i < 8; i++) {
            float4 o0, o1;
            o0.x = acc2[i][0]; o0.y = acc2[i][1]; o0.z = acc2[i][2]; o0.w = acc2[i][3];
            o1.x = acc2[i][4]; o1.y = acc2[i][5]; o1.z = acc2[i][6]; o1.w = acc2[i][7];
            float* op = &o[(size_t)(tm + i) * SS + n0 + tn];
            *(float4*)(op)     = o0;
            *(float4*)(op + 4) = o1;
        }
    }
}

// ---------------------------------------------------------------------------
// Launch: qkv projections -> attention -> output projection.
// Output tuple order: out, k, v (concatenated in d_out).
// ---------------------------------------------------------------------------
extern "C" void kernel_launch(void* const* d_in, const int* in_sizes, int n_in,
                              void* d_out, int out_size)
{
    const float* hs = (const float*)d_in[0];
    const float* Wq = (const float*)d_in[1];
    const float* bq = (const float*)d_in[2];
    const float* Wk = (const float*)d_in[3];
    const float* bk = (const float*)d_in[4];
    const float* Wv = (const float*)d_in[5];
    const float* bv = (const float*)d_in[6];
    const float* Wo = (const float*)d_in[7];
    const float* bo = (const float*)d_in[8];

    float *qbuf, *abuf, *kfb, *vfb;
    cudaGetSymbolAddress((void**)&qbuf, g_q);
    cudaGetSymbolAddress((void**)&abuf, g_attn);
    cudaGetSymbolAddress((void**)&kfb,  g_kfb);
    cudaGetSymbolAddress((void**)&vfb,  g_vfb);

    float* out = (float*)d_out;
    float* kout;
    float* vout;
    if ((long long)out_size >= 3LL * BHS) {
        kout = out + (size_t)BHS;
        vout = out + 2 * (size_t)BHS;
    } else {
        kout = kfb;
        vout = vfb;
    }

    dim3 blk(256, 1, 1);
    dim3 grid(SS / TN, CH / TM, BB);

    gemm_bias_kernel<<<grid, blk>>>(Wq, hs, bq, qbuf, CH, SS, CH);
    gemm_bias_kernel<<<grid, blk>>>(Wk, hs, bk, kout, CH, SS, CH);
    gemm_bias_kernel<<<grid, blk>>>(Wv, hs, bv, vout, CH, SS, CH);

    const int attn_smem = (128 * 128 + 2 * 16 * VPAD) * (int)sizeof(float); // 82432
    cudaFuncSetAttribute(attn_kernel,
                         cudaFuncAttributeMaxDynamicSharedMemorySize, attn_smem);
    attn_kernel<<<BB * NH, 256, attn_smem>>>(qbuf, kout, vout, abuf);

    gemm_bias_kernel<<<grid, blk>>>(Wo, abuf, bo, out, CH, SS, CH);
}

// round 3
// speedup vs baseline: 4.5823x; 4.5823x over previous
#include <cuda_runtime.h>
#include <math.h>
#include <stdint.h>

// Problem constants
#define BB 4
#define CH 4096     // HID
#define SSZ 2048    // S
#define NH 32       // heads
#define HD 128      // head dim

#define BHS 33554432   // BB*CH*SSZ elements
#define WSZ 16777216   // CH*CH elements

// Scratch (allocation-free rule: __device__ globals)
__device__ float g_q[BHS];      // Q projection [b][ch][s]
__device__ float g_attnT[BHS];  // attention out, transposed+rounded [b][s][ch]
__device__ float g_kfb[BHS];    // fallback K dest
__device__ float g_vfb[BHS];    // fallback V dest
__device__ float g_xt[BHS];     // hidden transposed+rounded [b][s][ch]
__device__ float g_wr[4 * WSZ]; // tf32-rounded Wq,Wk,Wv,Wo

// ===========================================================================
// Helpers
// ===========================================================================
__device__ __forceinline__ uint32_t smem_u32(const void* p) {
    uint32_t a;
    asm("{ .reg .u64 t; cvta.to.shared.u64 t, %1; cvt.u32.u64 %0, t; }"
        : "=r"(a) : "l"(p));
    return a;
}

__device__ __forceinline__ float f2tf32f(float f) {
    uint32_t u;
    asm("cvt.rna.tf32.f32 %0, %1;" : "=r"(u) : "f"(f));
    return __uint_as_float(u);
}

__device__ __forceinline__ uint32_t lds32(uint32_t a) {
    uint32_t v;
    asm("ld.shared.b32 %0, [%1];" : "=r"(v) : "r"(a));
    return v;
}

__device__ __forceinline__ void cp16(uint32_t dst, const void* src) {
    asm volatile("cp.async.cg.shared.global [%0], [%1], 16;"
                 :: "r"(dst), "l"(src) : "memory");
}
#define CP_COMMIT() asm volatile("cp.async.commit_group;" ::: "memory")
#define CP_WAIT(n)  asm volatile("cp.async.wait_group %0;" :: "n"(n) : "memory")

// mma.sync m16n8k8 tf32: D += A*B (row.col), accum fp32
__device__ __forceinline__ void mma_tf32(float* d, const uint32_t* a, const uint32_t* b) {
    asm volatile(
        "mma.sync.aligned.m16n8k8.row.col.f32.tf32.tf32.f32 "
        "{%0,%1,%2,%3}, {%4,%5,%6,%7}, {%8,%9}, {%0,%1,%2,%3};"
        : "+f"(d[0]), "+f"(d[1]), "+f"(d[2]), "+f"(d[3])
        : "r"(a[0]), "r"(a[1]), "r"(a[2]), "r"(a[3]), "r"(b[0]), "r"(b[1]));
}

// ===========================================================================
// Prep kernels
// ===========================================================================
__global__ void round_tf32_kernel(const float* __restrict__ W, float* __restrict__ Wr) {
    size_t i = ((size_t)blockIdx.x * 256 + threadIdx.x) * 4;
    float4 v = *(const float4*)(W + i);
    v.x = f2tf32f(v.x); v.y = f2tf32f(v.y);
    v.z = f2tf32f(v.z); v.w = f2tf32f(v.w);
    *(float4*)(Wr + i) = v;
}

// X [b][ch][s] -> Xt [b][s][ch], tf32-rounded
__global__ void transpose_round_kernel(const float* __restrict__ X, float* __restrict__ Xt) {
    __shared__ float tile[32][33];
    const int b  = blockIdx.z;
    const int k0 = blockIdx.y * 32;   // ch
    const int n0 = blockIdx.x * 32;   // s
    const float* Xb  = X  + (size_t)b * CH * SSZ;
    float*       Xtb = Xt + (size_t)b * SSZ * CH;
    const int tx = threadIdx.x & 31;
    const int ty = threadIdx.x >> 5;  // 0..7
#pragma unroll
    for (int i = 0; i < 4; i++)
        tile[ty + i * 8][tx] = Xb[(size_t)(k0 + ty + i * 8) * SSZ + n0 + tx];
    __syncthreads();
#pragma unroll
    for (int i = 0; i < 4; i++)
        Xtb[(size_t)(n0 + ty + i * 8) * CH + k0 + tx] =
            f2tf32f(tile[tx][ty + i * 8]);
}

// ===========================================================================
// Tensor-core GEMM via mma.sync tf32:
//   Y[b] (CH x SSZ) = A (CH x CH, tf32-rounded, row-major K-contig)
//                   @ Bt[b]^T  where Bt is (SSZ x CH, tf32-rounded, K-contig)
//   + bias.
// CTA 128x128, K-chunk 32, 3-stage cp.async pipeline, 8 warps (2Mx4N),
// warp tile 64x32 (4 m16 x 4 n8 tiles).
// SMEM per stage: A 128x36 fl + B 128x36 fl = 36864 B; 3 stages = 110592 B.
// ===========================================================================
#define STAGE_BYTES 36864
#define SMEM_GEMM_TOTAL (3 * STAGE_BYTES)

__global__ __launch_bounds__(256, 2) void gemm_mma(
    const float* __restrict__ A, const float* __restrict__ Bt,
    const float* __restrict__ bias, float* __restrict__ Y)
{
    extern __shared__ char smem[];
    const uint32_t sb = smem_u32(smem);
    const int t    = threadIdx.x;
    const int lane = t & 31;
    const int wid  = t >> 5;
    const int wm   = wid >> 2;       // 0..1
    const int wn   = wid & 3;        // 0..3
    const int m0 = blockIdx.y * 128;
    const int n0 = blockIdx.x * 128;
    const float* Bb = Bt + (size_t)blockIdx.z * SSZ * CH;
    float*       Yb = Y  + (size_t)blockIdx.z * CH * SSZ;

    const int lr = t >> 3;           // 0..31 (row within 32-row group)
    const int lq = (t & 7) * 4;      // k offset (floats)

    float acc[4][4][4];
#pragma unroll
    for (int mt = 0; mt < 4; mt++)
#pragma unroll
        for (int nt = 0; nt < 4; nt++)
#pragma unroll
            for (int x = 0; x < 4; x++) acc[mt][nt][x] = 0.0f;

    auto issue = [&](int chunk) {
        const int stage = chunk % 3;
        const int k0 = chunk * 32;
        const uint32_t As = sb + stage * STAGE_BYTES;
        const uint32_t Bs = As + 18432;
#pragma unroll
        for (int it = 0; it < 4; it++) {
            int m = it * 32 + lr;
            cp16(As + (uint32_t)(m * 36 + lq) * 4,
                 A + (size_t)(m0 + m) * CH + k0 + lq);
        }
#pragma unroll
        for (int it = 0; it < 4; it++) {
            int n = it * 32 + lr;
            cp16(Bs + (uint32_t)(n * 36 + lq) * 4,
                 Bb + (size_t)(n0 + n) * CH + k0 + lq);
        }
        CP_COMMIT();
    };

    issue(0); issue(1); issue(2);

    const int r = lane >> 2;   // 0..7
    const int c = lane & 3;    // 0..3

    for (int i = 0; i < 128; i++) {
        CP_WAIT(2);
        __syncthreads();
        const uint32_t As = sb + (i % 3) * STAGE_BYTES;
        const uint32_t Bs = As + 18432;
#pragma unroll
        for (int ks = 0; ks < 4; ks++) {
            uint32_t a[4][4], b[4][2];
#pragma unroll
            for (int mt = 0; mt < 4; mt++) {
                uint32_t base = As +
                    (uint32_t)((wm * 64 + mt * 16 + r) * 36 + ks * 8 + c) * 4;
                a[mt][0] = lds32(base);
                a[mt][1] = lds32(base + 8 * 36 * 4);
                a[mt][2] = lds32(base + 16);
                a[mt][3] = lds32(base + 8 * 36 * 4 + 16);
            }
#pragma unroll
            for (int nt = 0; nt < 4; nt++) {
                uint32_t base = Bs +
                    (uint32_t)((wn * 32 + nt * 8 + r) * 36 + ks * 8 + c) * 4;
                b[nt][0] = lds32(base);
                b[nt][1] = lds32(base + 16);
            }
#pragma unroll
            for (int mt = 0; mt < 4; mt++)
#pragma unroll
                for (int nt = 0; nt < 4; nt++)
                    mma_tf32(acc[mt][nt], a[mt], b[nt]);
        }
        __syncthreads();
        if (i + 3 < 128) issue(i + 3);
        else CP_COMMIT();   // empty group keeps wait_group accounting exact
    }

    // Epilogue: bias + direct stores (fragment rows r, r+8; cols 2c, 2c+1)
#pragma unroll
    for (int mt = 0; mt < 4; mt++) {
        int row0 = m0 + wm * 64 + mt * 16 + r;
        float bv0 = bias[row0];
        float bv1 = bias[row0 + 8];
#pragma unroll
        for (int nt = 0; nt < 4; nt++) {
            int col = n0 + wn * 32 + nt * 8 + c * 2;
            float2 v0 = make_float2(acc[mt][nt][0] + bv0, acc[mt][nt][1] + bv0);
            float2 v1 = make_float2(acc[mt][nt][2] + bv1, acc[mt][nt][3] + bv1);
            *(float2*)&Yb[(size_t)row0 * SSZ + col]       = v0;
            *(float2*)&Yb[(size_t)(row0 + 8) * SSZ + col] = v1;
        }
    }
}

// ===========================================================================
// Attention per (b,h); epilogue writes TRANSPOSED + tf32-rounded [s][ch]
// ===========================================================================
#define VPAD 132

__global__ __launch_bounds__(256, 1) void attn_kernel(
    const float* __restrict__ Q, const float* __restrict__ Kt,
    const float* __restrict__ V, float* __restrict__ OT)
{
    extern __shared__ float sm[];
    float* p_s  = sm;
    float* bufA = sm + 128 * 128;
    float* bufB = bufA + 16 * VPAD;

    const int bh = blockIdx.x;
    const size_t base = (size_t)bh * HD * SSZ;
    const float* q = Q  + base;
    const float* k = Kt + base;
    const float* v = V  + base;
    const int b_ = bh >> 5, h_ = bh & 31;
    float* oT = OT + (size_t)b_ * SSZ * CH + h_ * HD;

    const int t  = threadIdx.x;
    const int tm = (t >> 4) << 3;
    const int tn = (t & 15) << 3;

    float acc[8][8];
#pragma unroll
    for (int i = 0; i < 8; i++)
#pragma unroll
        for (int j = 0; j < 8; j++) acc[i][j] = 0.0f;

    for (int s0 = 0; s0 < SSZ; s0 += 16) {
#pragma unroll
        for (int i = 0; i < 8; i++) {
            int idx = i * 256 + t;
            int d   = idx >> 4;
            int sk  = idx & 15;
            bufA[sk * VPAD + d] = q[(size_t)d * SSZ + s0 + sk];
            bufB[sk * VPAD + d] = k[(size_t)d * SSZ + s0 + sk];
        }
        __syncthreads();
#pragma unroll 4
        for (int sk = 0; sk < 16; sk++) {
            float a[8], b[8];
#pragma unroll
            for (int i = 0; i < 8; i++) a[i] = bufA[sk * VPAD + tm + i];
#pragma unroll
            for (int j = 0; j < 8; j++) b[j] = bufB[sk * VPAD + tn + j];
#pragma unroll
            for (int i = 0; i < 8; i++)
#pragma unroll
                for (int j = 0; j < 8; j++) acc[i][j] += a[i] * b[j];
        }
        __syncthreads();
    }

    const float scale = rsqrtf((float)SSZ);
#pragma unroll
    for (int i = 0; i < 8; i++)
#pragma unroll
        for (int j = 0; j < 8; j++) {
            int rr = tm + i, cc = tn + j;
            p_s[rr * 128 + cc] = (cc <= rr) ? acc[i][j] * scale : 0.0f;
        }
    __syncthreads();

    if (t < 128) {
        float* row = &p_s[t * 128];
        float mx = -3.0e38f;
        for (int e = 0; e <= t; e++) mx = fmaxf(mx, row[e]);
        float sum = 0.0f;
        for (int e = 0; e <= t; e++) {
            float ex = __expf(row[e] - mx);
            row[e] = ex;
            sum += ex;
        }
        float inv = 1.0f / sum;
        for (int e = 0; e <= t; e++) row[e] *= inv;
    }
    __syncthreads();

    for (int n0 = 0; n0 < SSZ; n0 += 128) {
        float acc2[8][8];
#pragma unroll
        for (int i = 0; i < 8; i++)
#pragma unroll
            for (int j = 0; j < 8; j++) acc2[i][j] = 0.0f;

        for (int e0 = 0; e0 < HD; e0 += 16) {
#pragma unroll
            for (int i = 0; i < 8; i++) {
                int idx = i * 256 + t;
                int ek  = idx >> 7;
                int col = idx & 127;
                bufA[ek * VPAD + col] = v[(size_t)(e0 + ek) * SSZ + n0 + col];
            }
            __syncthreads();
#pragma unroll 4
            for (int ek = 0; ek < 16; ek++) {
                float a[8], b[8];
#pragma unroll
                for (int i = 0; i < 8; i++) a[i] = p_s[(tm + i) * 128 + e0 + ek];
#pragma unroll
                for (int j = 0; j < 8; j++) b[j] = bufA[ek * VPAD + tn + j];
#pragma unroll
                for (int i = 0; i < 8; i++)
#pragma unroll
                    for (int j = 0; j < 8; j++) acc2[i][j] += a[i] * b[j];
            }
            __syncthreads();
        }

        // Transposed + rounded store: oT[s][h*128 + d]
#pragma unroll
        for (int j = 0; j < 8; j++) {
            int s = n0 + tn + j;
            float4 lo, hi;
            lo.x = f2tf32f(acc2[0][j]); lo.y = f2tf32f(acc2[1][j]);
            lo.z = f2tf32f(acc2[2][j]); lo.w = f2tf32f(acc2[3][j]);
            hi.x = f2tf32f(acc2[4][j]); hi.y = f2tf32f(acc2[5][j]);
            hi.z = f2tf32f(acc2[6][j]); hi.w = f2tf32f(acc2[7][j]);
            *(float4*)&oT[(size_t)s * CH + tm]     = lo;
            *(float4*)&oT[(size_t)s * CH + tm + 4] = hi;
        }
    }
}

// ===========================================================================
// Launch
// ===========================================================================
extern "C" void kernel_launch(void* const* d_in, const int* in_sizes, int n_in,
                              void* d_out, int out_size)
{
    const float* hs = (const float*)d_in[0];
    const float* Wq = (const float*)d_in[1];
    const float* bq = (const float*)d_in[2];
    const float* Wk = (const float*)d_in[3];
    const float* bk = (const float*)d_in[4];
    const float* Wv = (const float*)d_in[5];
    const float* bv = (const float*)d_in[6];
    const float* Wo = (const float*)d_in[7];
    const float* bo = (const float*)d_in[8];

    float *qbuf, *atbuf, *kfb, *vfb, *xt, *wr;
    cudaGetSymbolAddress((void**)&qbuf,  g_q);
    cudaGetSymbolAddress((void**)&atbuf, g_attnT);
    cudaGetSymbolAddress((void**)&kfb,   g_kfb);
    cudaGetSymbolAddress((void**)&vfb,   g_vfb);
    cudaGetSymbolAddress((void**)&xt,    g_xt);
    cudaGetSymbolAddress((void**)&wr,    g_wr);

    float* out = (float*)d_out;
    float* kout;
    float* vout;
    if ((long long)out_size >= 3LL * BHS) {
        kout = out + (size_t)BHS;
        vout = out + 2 * (size_t)BHS;
    } else {
        kout = kfb;
        vout = vfb;
    }

    // ---- Prep: round weights, transpose+round hidden ----
    const int rblocks = WSZ / (256 * 4);   // 16384
    round_tf32_kernel<<<rblocks, 256>>>(Wq, wr + 0 * (size_t)WSZ);
    round_tf32_kernel<<<rblocks, 256>>>(Wk, wr + 1 * (size_t)WSZ);
    round_tf32_kernel<<<rblocks, 256>>>(Wv, wr + 2 * (size_t)WSZ);
    round_tf32_kernel<<<rblocks, 256>>>(Wo, wr + 3 * (size_t)WSZ);
    transpose_round_kernel<<<dim3(SSZ / 32, CH / 32, BB), 256>>>(hs, xt);

    // ---- Projections ----
    cudaFuncSetAttribute(gemm_mma,
                         cudaFuncAttributeMaxDynamicSharedMemorySize, SMEM_GEMM_TOTAL);
    dim3 blk(256, 1, 1);
    dim3 grid(SSZ / 128, CH / 128, BB);   // (16, 32, 4)

    gemm_mma<<<grid, blk, SMEM_GEMM_TOTAL>>>(wr + 0 * (size_t)WSZ, xt, bq, qbuf);
    gemm_mma<<<grid, blk, SMEM_GEMM_TOTAL>>>(wr + 1 * (size_t)WSZ, xt, bk, kout);
    gemm_mma<<<grid, blk, SMEM_GEMM_TOTAL>>>(wr + 2 * (size_t)WSZ, xt, bv, vout);

    // ---- Attention ----
    const int attn_smem = (128 * 128 + 2 * 16 * VPAD) * (int)sizeof(float);
    cudaFuncSetAttribute(attn_kernel,
                         cudaFuncAttributeMaxDynamicSharedMemorySize, attn_smem);
    attn_kernel<<<BB * NH, 256, attn_smem>>>(qbuf, kout, vout, atbuf);

    // ---- Output projection ----
    gemm_mma<<<grid, blk, SMEM_GEMM_TOTAL>>>(wr + 3 * (size_t)WSZ, atbuf, bo, out);
}

// round 4
// speedup vs baseline: 10.6700x; 2.3285x over previous
#include <cuda_runtime.h>
#include <cuda_fp16.h>
#include <math.h>
#include <stdint.h>

// Problem constants
#define BB 4
#define CH 4096     // HID
#define SSZ 2048    // S
#define NH 32       // heads
#define HD 128      // head dim

#define BHS 33554432   // BB*CH*SSZ elements
#define WSZ 16777216   // CH*CH elements

// Scratch (allocation-free rule: __device__ globals)
__device__ float  g_q[BHS];       // Q projection [b][ch][s] fp32
__device__ __half g_attnTh[BHS];  // attention out, transposed half [b][s][ch]
__device__ __half g_xth[BHS];     // hidden transposed half [b][s][ch]
__device__ __half g_wh[4 * WSZ];  // half Wq,Wk,Wv,Wo (row-major, K-contig)
__device__ float  g_kfb[BHS];     // fallback K dest
__device__ float  g_vfb[BHS];     // fallback V dest

// ===========================================================================
// Helpers
// ===========================================================================
__device__ __forceinline__ uint32_t smem_u32(const void* p) {
    uint32_t a;
    asm("{ .reg .u64 t; cvta.to.shared.u64 t, %1; cvt.u32.u64 %0, t; }"
        : "=r"(a) : "l"(p));
    return a;
}

__device__ __forceinline__ void cp16(uint32_t dst, const void* src) {
    asm volatile("cp.async.cg.shared.global [%0], [%1], 16;"
                 :: "r"(dst), "l"(src) : "memory");
}
#define CP_COMMIT() asm volatile("cp.async.commit_group;" ::: "memory")
#define CP_WAIT(n)  asm volatile("cp.async.wait_group %0;" :: "n"(n) : "memory")

__device__ __forceinline__ void ldsm_x4(uint32_t& r0, uint32_t& r1,
                                        uint32_t& r2, uint32_t& r3, uint32_t addr) {
    asm volatile("ldmatrix.sync.aligned.m8n8.x4.shared.b16 {%0,%1,%2,%3}, [%4];"
                 : "=r"(r0), "=r"(r1), "=r"(r2), "=r"(r3) : "r"(addr));
}

// mma m16n8k16 f16 inputs, f32 accumulate
__device__ __forceinline__ void mma_f16(float* d, const uint32_t* a, const uint32_t* b) {
    asm volatile(
        "mma.sync.aligned.m16n8k16.row.col.f32.f16.f16.f32 "
        "{%0,%1,%2,%3}, {%4,%5,%6,%7}, {%8,%9}, {%0,%1,%2,%3};"
        : "+f"(d[0]), "+f"(d[1]), "+f"(d[2]), "+f"(d[3])
        : "r"(a[0]), "r"(a[1]), "r"(a[2]), "r"(a[3]), "r"(b[0]), "r"(b[1]));
}

// ===========================================================================
// Prep kernels
// ===========================================================================
// 8 floats -> 8 halves per thread
__global__ void round_half_kernel(const float* __restrict__ W, __half* __restrict__ Wh) {
    size_t i = ((size_t)blockIdx.x * 256 + threadIdx.x) * 8;
    float4 v0 = *(const float4*)(W + i);
    float4 v1 = *(const float4*)(W + i + 4);
    __half2 h0 = __floats2half2_rn(v0.x, v0.y);
    __half2 h1 = __floats2half2_rn(v0.z, v0.w);
    __half2 h2 = __floats2half2_rn(v1.x, v1.y);
    __half2 h3 = __floats2half2_rn(v1.z, v1.w);
    uint4 o;
    o.x = *(uint32_t*)&h0; o.y = *(uint32_t*)&h1;
    o.z = *(uint32_t*)&h2; o.w = *(uint32_t*)&h3;
    *(uint4*)(Wh + i) = o;
}

// X [b][ch][s] fp32 -> Xt [b][s][ch] half
__global__ void transpose_half_kernel(const float* __restrict__ X, __half* __restrict__ Xt) {
    __shared__ float tile[32][33];
    const int b  = blockIdx.z;
    const int k0 = blockIdx.y * 32;   // ch
    const int n0 = blockIdx.x * 32;   // s
    const float* Xb  = X  + (size_t)b * CH * SSZ;
    __half*      Xtb = Xt + (size_t)b * SSZ * CH;
    const int tx = threadIdx.x & 31;
    const int ty = threadIdx.x >> 5;  // 0..7
#pragma unroll
    for (int i = 0; i < 4; i++)
        tile[ty + i * 8][tx] = Xb[(size_t)(k0 + ty + i * 8) * SSZ + n0 + tx];
    __syncthreads();
#pragma unroll
    for (int i = 0; i < 4; i++)
        Xtb[(size_t)(n0 + ty + i * 8) * CH + k0 + tx] =
            __float2half_rn(tile[tx][ty + i * 8]);
}

// ===========================================================================
// fp16 tensor-core GEMM core:
//   Y (row m=output-ch, col n=s) = A(M x K half, row-major) @ Bt^T + bias
//   Bt is (N x K half, row-major).
// CTA 128x128, K-chunk 64, 3-stage cp.async, 8 warps (2Mx4N), warp 64x32.
// SMEM/stage: A 128x64 half (16KB) + B 128x64 half (16KB) = 32KB; xor swizzle.
// ===========================================================================
#define STAGE_H 32768
#define SMEM_H  (3 * STAGE_H)   // 98304

__device__ __forceinline__ void gemm_core_h(
    const __half* __restrict__ A, const __half* __restrict__ Bb,
    const float* __restrict__ bias, float* __restrict__ Yb,
    int m0, int n0, char* smem)
{
    const uint32_t sb = smem_u32(smem);
    const int t    = threadIdx.x;
    const int lane = t & 31;
    const int wid  = t >> 5;
    const int wm   = wid >> 2;   // 0..1
    const int wn   = wid & 3;    // 0..3
    const int lr = t >> 3;       // 0..31 (row group for cp.async)
    const int lc = t & 7;        // 16B chunk 0..7

    float acc[4][4][4];
#pragma unroll
    for (int mt = 0; mt < 4; mt++)
#pragma unroll
        for (int nt = 0; nt < 4; nt++)
#pragma unroll
            for (int x = 0; x < 4; x++) acc[mt][nt][x] = 0.0f;

    auto issue = [&](int chunk) {
        const int stage = chunk % 3;
        const int k0 = chunk * 64;
        const uint32_t As = sb + stage * STAGE_H;
        const uint32_t Bs = As + 16384;
#pragma unroll
        for (int it = 0; it < 4; it++) {
            int m = it * 32 + lr;
            cp16(As + (uint32_t)(m * 128 + ((lc ^ (m & 7)) << 4)),
                 A + (size_t)(m0 + m) * CH + k0 + lc * 8);
        }
#pragma unroll
        for (int it = 0; it < 4; it++) {
            int n = it * 32 + lr;
            cp16(Bs + (uint32_t)(n * 128 + ((lc ^ (n & 7)) << 4)),
                 Bb + (size_t)(n0 + n) * CH + k0 + lc * 8);
        }
        CP_COMMIT();
    };

    issue(0); issue(1); issue(2);

    for (int i = 0; i < 64; i++) {
        CP_WAIT(2);
        __syncthreads();
        const uint32_t As = sb + (i % 3) * STAGE_H;
        const uint32_t Bs = As + 16384;
#pragma unroll
        for (int ks = 0; ks < 4; ks++) {
            uint32_t a[4][4], b[2][4];
#pragma unroll
            for (int mt = 0; mt < 4; mt++) {
                int row = wm * 64 + mt * 16 + (lane & 15);
                int ch  = ks * 2 + (lane >> 4);
                uint32_t addr = As + row * 128 + ((ch ^ (row & 7)) << 4);
                ldsm_x4(a[mt][0], a[mt][1], a[mt][2], a[mt][3], addr);
            }
#pragma unroll
            for (int p = 0; p < 2; p++) {
                int row = wn * 32 + p * 16 + ((lane >> 4) << 3) + (lane & 7);
                int ch  = ks * 2 + ((lane >> 3) & 1);
                uint32_t addr = Bs + row * 128 + ((ch ^ (row & 7)) << 4);
                ldsm_x4(b[p][0], b[p][1], b[p][2], b[p][3], addr);
            }
#pragma unroll
            for (int mt = 0; mt < 4; mt++)
#pragma unroll
                for (int nt = 0; nt < 4; nt++)
                    mma_f16(acc[mt][nt], a[mt], &b[nt >> 1][(nt & 1) * 2]);
        }
        __syncthreads();
        if (i + 3 < 64) issue(i + 3);
        else CP_COMMIT();   // keep wait_group accounting exact
    }

    const int r = lane >> 2;   // 0..7
    const int c = lane & 3;    // 0..3
#pragma unroll
    for (int mt = 0; mt < 4; mt++) {
        int row0 = m0 + wm * 64 + mt * 16 + r;
        float bv0 = bias[row0];
        float bv1 = bias[row0 + 8];
#pragma unroll
        for (int nt = 0; nt < 4; nt++) {
            int col = n0 + wn * 32 + nt * 8 + c * 2;
            float2 v0 = make_float2(acc[mt][nt][0] + bv0, acc[mt][nt][1] + bv0);
            float2 v1 = make_float2(acc[mt][nt][2] + bv1, acc[mt][nt][3] + bv1);
            *(float2*)&Yb[(size_t)row0 * SSZ + col]       = v0;
            *(float2*)&Yb[(size_t)(row0 + 8) * SSZ + col] = v1;
        }
    }
}

// Fused Q/K/V projections: grid.y in [0,96); widx = y>>5 selects W/bias/out.
__global__ __launch_bounds__(256, 2) void gemm_qkv(
    const __half* __restrict__ Wh, const __half* __restrict__ Xt,
    const float* __restrict__ bq, const float* __restrict__ bk,
    const float* __restrict__ bv,
    float* __restrict__ Yq, float* __restrict__ Yk, float* __restrict__ Yv)
{
    extern __shared__ char smem[];
    const int widx = blockIdx.y >> 5;
    const int m0 = (blockIdx.y & 31) * 128;
    const int n0 = blockIdx.x * 128;
    const __half* A = Wh + (size_t)widx * WSZ;
    const float* bias = (widx == 0) ? bq : (widx == 1) ? bk : bv;
    float* Y = (widx == 0) ? Yq : (widx == 1) ? Yk : Yv;
    const __half* Bb = Xt + (size_t)blockIdx.z * SSZ * CH;
    float*        Yb = Y  + (size_t)blockIdx.z * CH * SSZ;
    gemm_core_h(A, Bb, bias, Yb, m0, n0, smem);
}

// Single GEMM (output projection)
__global__ __launch_bounds__(256, 2) void gemm_one(
    const __half* __restrict__ A, const __half* __restrict__ Bt,
    const float* __restrict__ bias, float* __restrict__ Y)
{
    extern __shared__ char smem[];
    const int m0 = blockIdx.y * 128;
    const int n0 = blockIdx.x * 128;
    const __half* Bb = Bt + (size_t)blockIdx.z * SSZ * CH;
    float*        Yb = Y  + (size_t)blockIdx.z * CH * SSZ;
    gemm_core_h(A, Bb, bias, Yb, m0, n0, smem);
}

// ===========================================================================
// Attention per (b,h); epilogue writes TRANSPOSED half [s][ch]
// ===========================================================================
#define VPAD 132

__global__ __launch_bounds__(256, 1) void attn_kernel(
    const float* __restrict__ Q, const float* __restrict__ Kt,
    const float* __restrict__ V, __half* __restrict__ OT)
{
    extern __shared__ float sm[];
    float* p_s  = sm;
    float* bufA = sm + 128 * 128;
    float* bufB = bufA + 16 * VPAD;

    const int bh = blockIdx.x;
    const size_t base = (size_t)bh * HD * SSZ;
    const float* q = Q  + base;
    const float* k = Kt + base;
    const float* v = V  + base;
    const int b_ = bh >> 5, h_ = bh & 31;
    __half* oT = OT + (size_t)b_ * SSZ * CH + h_ * HD;

    const int t  = threadIdx.x;
    const int tm = (t >> 4) << 3;
    const int tn = (t & 15) << 3;

    float acc[8][8];
#pragma unroll
    for (int i = 0; i < 8; i++)
#pragma unroll
        for (int j = 0; j < 8; j++) acc[i][j] = 0.0f;

    for (int s0 = 0; s0 < SSZ; s0 += 16) {
#pragma unroll
        for (int i = 0; i < 8; i++) {
            int idx = i * 256 + t;
            int d   = idx >> 4;
            int sk  = idx & 15;
            bufA[sk * VPAD + d] = q[(size_t)d * SSZ + s0 + sk];
            bufB[sk * VPAD + d] = k[(size_t)d * SSZ + s0 + sk];
        }
        __syncthreads();
#pragma unroll 4
        for (int sk = 0; sk < 16; sk++) {
            float a[8], b[8];
#pragma unroll
            for (int i = 0; i < 8; i++) a[i] = bufA[sk * VPAD + tm + i];
#pragma unroll
            for (int j = 0; j < 8; j++) b[j] = bufB[sk * VPAD + tn + j];
#pragma unroll
            for (int i = 0; i < 8; i++)
#pragma unroll
                for (int j = 0; j < 8; j++) acc[i][j] += a[i] * b[j];
        }
        __syncthreads();
    }

    const float scale = rsqrtf((float)SSZ);
#pragma unroll
    for (int i = 0; i < 8; i++)
#pragma unroll
        for (int j = 0; j < 8; j++) {
            int rr = tm + i, cc = tn + j;
            p_s[rr * 128 + cc] = (cc <= rr) ? acc[i][j] * scale : 0.0f;
        }
    __syncthreads();

    if (t < 128) {
        float* row = &p_s[t * 128];
        float mx = -3.0e38f;
        for (int e = 0; e <= t; e++) mx = fmaxf(mx, row[e]);
        float sum = 0.0f;
        for (int e = 0; e <= t; e++) {
            float ex = __expf(row[e] - mx);
            row[e] = ex;
            sum += ex;
        }
        float inv = 1.0f / sum;
        for (int e = 0; e <= t; e++) row[e] *= inv;
    }
    __syncthreads();

    for (int n0 = 0; n0 < SSZ; n0 += 128) {
        float acc2[8][8];
#pragma unroll
        for (int i = 0; i < 8; i++)
#pragma unroll
            for (int j = 0; j < 8; j++) acc2[i][j] = 0.0f;

        for (int e0 = 0; e0 < HD; e0 += 16) {
#pragma unroll
            for (int i = 0; i < 8; i++) {
                int idx = i * 256 + t;
                int ek  = idx >> 7;
                int col = idx & 127;
                bufA[ek * VPAD + col] = v[(size_t)(e0 + ek) * SSZ + n0 + col];
            }
            __syncthreads();
#pragma unroll 4
            for (int ek = 0; ek < 16; ek++) {
                float a[8], b[8];
#pragma unroll
                for (int i = 0; i < 8; i++) a[i] = p_s[(tm + i) * 128 + e0 + ek];
#pragma unroll
                for (int j = 0; j < 8; j++) b[j] = bufA[ek * VPAD + tn + j];
#pragma unroll
                for (int i = 0; i < 8; i++)
#pragma unroll
                    for (int j = 0; j < 8; j++) acc2[i][j] += a[i] * b[j];
            }
            __syncthreads();
        }

        // Transposed half store: oT[s][h*128 + d]
#pragma unroll
        for (int j = 0; j < 8; j++) {
            int s = n0 + tn + j;
            __half2 h0 = __floats2half2_rn(acc2[0][j], acc2[1][j]);
            __half2 h1 = __floats2half2_rn(acc2[2][j], acc2[3][j]);
            __half2 h2 = __floats2half2_rn(acc2[4][j], acc2[5][j]);
            __half2 h3 = __floats2half2_rn(acc2[6][j], acc2[7][j]);
            uint4 o;
            o.x = *(uint32_t*)&h0; o.y = *(uint32_t*)&h1;
            o.z = *(uint32_t*)&h2; o.w = *(uint32_t*)&h3;
            *(uint4*)&oT[(size_t)s * CH + tm] = o;
        }
    }
}

// ===========================================================================
// Launch
// ===========================================================================
extern "C" void kernel_launch(void* const* d_in, const int* in_sizes, int n_in,
                              void* d_out, int out_size)
{
    const float* hs = (const float*)d_in[0];
    const float* Wq = (const float*)d_in[1];
    const float* bq = (const float*)d_in[2];
    const float* Wk = (const float*)d_in[3];
    const float* bk = (const float*)d_in[4];
    const float* Wv = (const float*)d_in[5];
    const float* bv = (const float*)d_in[6];
    const float* Wo = (const float*)d_in[7];
    const float* bo = (const float*)d_in[8];

    float *qbuf, *kfb, *vfb;
    __half *atbufh, *xth, *wh;
    cudaGetSymbolAddress((void**)&qbuf,   g_q);
    cudaGetSymbolAddress((void**)&atbufh, g_attnTh);
    cudaGetSymbolAddress((void**)&xth,    g_xth);
    cudaGetSymbolAddress((void**)&wh,     g_wh);
    cudaGetSymbolAddress((void**)&kfb,    g_kfb);
    cudaGetSymbolAddress((void**)&vfb,    g_vfb);

    float* out = (float*)d_out;
    float* kout;
    float* vout;
    if ((long long)out_size >= 3LL * BHS) {
        kout = out + (size_t)BHS;
        vout = out + 2 * (size_t)BHS;
    } else {
        kout = kfb;
        vout = vfb;
    }

    // ---- Prep: halve weights, transpose+halve hidden ----
    const int rblocks = WSZ / (256 * 8);   // 8192
    round_half_kernel<<<rblocks, 256>>>(Wq, wh + 0 * (size_t)WSZ);
    round_half_kernel<<<rblocks, 256>>>(Wk, wh + 1 * (size_t)WSZ);
    round_half_kernel<<<rblocks, 256>>>(Wv, wh + 2 * (size_t)WSZ);
    round_half_kernel<<<rblocks, 256>>>(Wo, wh + 3 * (size_t)WSZ);
    transpose_half_kernel<<<dim3(SSZ / 32, CH / 32, BB), 256>>>(hs, xth);

    // ---- Fused Q/K/V projections ----
    cudaFuncSetAttribute(gemm_qkv,
                         cudaFuncAttributeMaxDynamicSharedMemorySize, SMEM_H);
    cudaFuncSetAttribute(gemm_one,
                         cudaFuncAttributeMaxDynamicSharedMemorySize, SMEM_H);
    dim3 blk(256, 1, 1);
    gemm_qkv<<<dim3(SSZ / 128, 96, BB), blk, SMEM_H>>>(
        wh, xth, bq, bk, bv, qbuf, kout, vout);

    // ---- Attention ----
    const int attn_smem = (128 * 128 + 2 * 16 * VPAD) * (int)sizeof(float);
    cudaFuncSetAttribute(attn_kernel,
                         cudaFuncAttributeMaxDynamicSharedMemorySize, attn_smem);
    attn_kernel<<<BB * NH, 256, attn_smem>>>(qbuf, kout, vout, atbufh);

    // ---- Output projection ----
    gemm_one<<<dim3(SSZ / 128, CH / 128, BB), blk, SMEM_H>>>(
        wh + 3 * (size_t)WSZ, atbufh, bo, out);
}

// round 5
// speedup vs baseline: 12.6019x; 1.1811x over previous
#include <cuda_runtime.h>
#include <cuda_fp16.h>
#include <math.h>
#include <stdint.h>

// Problem constants
#define BB 4
#define CH 4096     // HID
#define SSZ 2048    // S
#define NH 32       // heads
#define HD 128      // head dim

#define BHS 33554432   // BB*CH*SSZ elements
#define WSZ 16777216   // CH*CH elements

// Scratch (allocation-free rule: __device__ globals)
__device__ __half g_qh[BHS];      // Q half [b][ch][s]
__device__ __half g_kh[BHS];      // K half [b][ch][s]
__device__ __half g_vh[BHS];      // V half [b][ch][s]
__device__ __half g_attnTh[BHS];  // attention out, transposed half [b][s][ch]
__device__ __half g_xth[BHS];     // hidden transposed half [b][s][ch]
__device__ __half g_wh[4 * WSZ];  // half Wq,Wk,Wv,Wo (row-major, K-contig)
__device__ float  g_kfb[BHS];     // fallback K dest
__device__ float  g_vfb[BHS];     // fallback V dest

// ===========================================================================
// Helpers
// ===========================================================================
__device__ __forceinline__ uint32_t smem_u32(const void* p) {
    uint32_t a;
    asm("{ .reg .u64 t; cvta.to.shared.u64 t, %1; cvt.u32.u64 %0, t; }"
        : "=r"(a) : "l"(p));
    return a;
}

__device__ __forceinline__ void cp16(uint32_t dst, const void* src) {
    asm volatile("cp.async.cg.shared.global [%0], [%1], 16;"
                 :: "r"(dst), "l"(src) : "memory");
}
#define CP_COMMIT() asm volatile("cp.async.commit_group;" ::: "memory")
#define CP_WAIT(n)  asm volatile("cp.async.wait_group %0;" :: "n"(n) : "memory")

__device__ __forceinline__ void ldsm_x4(uint32_t& r0, uint32_t& r1,
                                        uint32_t& r2, uint32_t& r3, uint32_t addr) {
    asm volatile("ldmatrix.sync.aligned.m8n8.x4.shared.b16 {%0,%1,%2,%3}, [%4];"
                 : "=r"(r0), "=r"(r1), "=r"(r2), "=r"(r3) : "r"(addr));
}

__device__ __forceinline__ void ldsm_x4_t(uint32_t& r0, uint32_t& r1,
                                          uint32_t& r2, uint32_t& r3, uint32_t addr) {
    asm volatile("ldmatrix.sync.aligned.m8n8.x4.trans.shared.b16 {%0,%1,%2,%3}, [%4];"
                 : "=r"(r0), "=r"(r1), "=r"(r2), "=r"(r3) : "r"(addr));
}

// mma m16n8k16 f16 inputs, f32 accumulate
__device__ __forceinline__ void mma_f16(float* d, const uint32_t* a, const uint32_t* b) {
    asm volatile(
        "mma.sync.aligned.m16n8k16.row.col.f32.f16.f16.f32 "
        "{%0,%1,%2,%3}, {%4,%5,%6,%7}, {%8,%9}, {%0,%1,%2,%3};"
        : "+f"(d[0]), "+f"(d[1]), "+f"(d[2]), "+f"(d[3])
        : "r"(a[0]), "r"(a[1]), "r"(a[2]), "r"(a[3]), "r"(b[0]), "r"(b[1]));
}

// ===========================================================================
// Prep kernels
// ===========================================================================
__global__ void round_half_kernel(const float* __restrict__ W, __half* __restrict__ Wh) {
    size_t i = ((size_t)blockIdx.x * 256 + threadIdx.x) * 8;
    float4 v0 = *(const float4*)(W + i);
    float4 v1 = *(const float4*)(W + i + 4);
    __half2 h0 = __floats2half2_rn(v0.x, v0.y);
    __half2 h1 = __floats2half2_rn(v0.z, v0.w);
    __half2 h2 = __floats2half2_rn(v1.x, v1.y);
    __half2 h3 = __floats2half2_rn(v1.z, v1.w);
    uint4 o;
    o.x = *(uint32_t*)&h0; o.y = *(uint32_t*)&h1;
    o.z = *(uint32_t*)&h2; o.w = *(uint32_t*)&h3;
    *(uint4*)(Wh + i) = o;
}

// X [b][ch][s] fp32 -> Xt [b][s][ch] half
__global__ void transpose_half_kernel(const float* __restrict__ X, __half* __restrict__ Xt) {
    __shared__ float tile[32][33];
    const int b  = blockIdx.z;
    const int k0 = blockIdx.y * 32;
    const int n0 = blockIdx.x * 32;
    const float* Xb  = X  + (size_t)b * CH * SSZ;
    __half*      Xtb = Xt + (size_t)b * SSZ * CH;
    const int tx = threadIdx.x & 31;
    const int ty = threadIdx.x >> 5;
#pragma unroll
    for (int i = 0; i < 4; i++)
        tile[ty + i * 8][tx] = Xb[(size_t)(k0 + ty + i * 8) * SSZ + n0 + tx];
    __syncthreads();
#pragma unroll
    for (int i = 0; i < 4; i++)
        Xtb[(size_t)(n0 + ty + i * 8) * CH + k0 + tx] =
            __float2half_rn(tile[tx][ty + i * 8]);
}

// ===========================================================================
// fp16 tensor-core GEMM core: Y = A(MxK) @ Bt(NxK)^T + bias
// CTA 128x128, K-chunk 64, 3-stage cp.async, 8 warps (2Mx4N), warp 64x32.
// Optional fp32 output Yf and/or half output Yh (same [row][col] layout).
// ===========================================================================
#define STAGE_H 32768
#define SMEM_H  (3 * STAGE_H)   // 98304

__device__ __forceinline__ void gemm_core_h(
    const __half* __restrict__ A, const __half* __restrict__ Bb,
    const float* __restrict__ bias, float* __restrict__ Yf,
    __half* __restrict__ Yh, int m0, int n0, char* smem)
{
    const uint32_t sb = smem_u32(smem);
    const int t    = threadIdx.x;
    const int lane = t & 31;
    const int wid  = t >> 5;
    const int wm   = wid >> 2;
    const int wn   = wid & 3;
    const int lr = t >> 3;
    const int lc = t & 7;

    float acc[4][4][4];
#pragma unroll
    for (int mt = 0; mt < 4; mt++)
#pragma unroll
        for (int nt = 0; nt < 4; nt++)
#pragma unroll
            for (int x = 0; x < 4; x++) acc[mt][nt][x] = 0.0f;

    auto issue = [&](int chunk) {
        const int stage = chunk % 3;
        const int k0 = chunk * 64;
        const uint32_t As = sb + stage * STAGE_H;
        const uint32_t Bs = As + 16384;
#pragma unroll
        for (int it = 0; it < 4; it++) {
            int m = it * 32 + lr;
            cp16(As + (uint32_t)(m * 128 + ((lc ^ (m & 7)) << 4)),
                 A + (size_t)(m0 + m) * CH + k0 + lc * 8);
        }
#pragma unroll
        for (int it = 0; it < 4; it++) {
            int n = it * 32 + lr;
            cp16(Bs + (uint32_t)(n * 128 + ((lc ^ (n & 7)) << 4)),
                 Bb + (size_t)(n0 + n) * CH + k0 + lc * 8);
        }
        CP_COMMIT();
    };

    issue(0); issue(1); issue(2);

    for (int i = 0; i < 64; i++) {
        CP_WAIT(2);
        __syncthreads();
        const uint32_t As = sb + (i % 3) * STAGE_H;
        const uint32_t Bs = As + 16384;
#pragma unroll
        for (int ks = 0; ks < 4; ks++) {
            uint32_t a[4][4], b[2][4];
#pragma unroll
            for (int mt = 0; mt < 4; mt++) {
                int row = wm * 64 + mt * 16 + (lane & 15);
                int ch  = ks * 2 + (lane >> 4);
                uint32_t addr = As + row * 128 + ((ch ^ (row & 7)) << 4);
                ldsm_x4(a[mt][0], a[mt][1], a[mt][2], a[mt][3], addr);
            }
#pragma unroll
            for (int p = 0; p < 2; p++) {
                int row = wn * 32 + p * 16 + ((lane >> 4) << 3) + (lane & 7);
                int ch  = ks * 2 + ((lane >> 3) & 1);
                uint32_t addr = Bs + row * 128 + ((ch ^ (row & 7)) << 4);
                ldsm_x4(b[p][0], b[p][1], b[p][2], b[p][3], addr);
            }
#pragma unroll
            for (int mt = 0; mt < 4; mt++)
#pragma unroll
                for (int nt = 0; nt < 4; nt++)
                    mma_f16(acc[mt][nt], a[mt], &b[nt >> 1][(nt & 1) * 2]);
        }
        __syncthreads();
        if (i + 3 < 64) issue(i + 3);
        else CP_COMMIT();
    }

    const int r = lane >> 2;
    const int c = lane & 3;
#pragma unroll
    for (int mt = 0; mt < 4; mt++) {
        int row0 = m0 + wm * 64 + mt * 16 + r;
        float bv0 = bias[row0];
        float bv1 = bias[row0 + 8];
#pragma unroll
        for (int nt = 0; nt < 4; nt++) {
            int col = n0 + wn * 32 + nt * 8 + c * 2;
            float f00 = acc[mt][nt][0] + bv0, f01 = acc[mt][nt][1] + bv0;
            float f10 = acc[mt][nt][2] + bv1, f11 = acc[mt][nt][3] + bv1;
            if (Yf) {
                *(float2*)&Yf[(size_t)row0 * SSZ + col]       = make_float2(f00, f01);
                *(float2*)&Yf[(size_t)(row0 + 8) * SSZ + col] = make_float2(f10, f11);
            }
            if (Yh) {
                __half2 h0 = __floats2half2_rn(f00, f01);
                __half2 h1 = __floats2half2_rn(f10, f11);
                *(__half2*)&Yh[(size_t)row0 * SSZ + col]       = h0;
                *(__half2*)&Yh[(size_t)(row0 + 8) * SSZ + col] = h1;
            }
        }
    }
}

// Fused Q/K/V projections.
__global__ __launch_bounds__(256, 2) void gemm_qkv(
    const __half* __restrict__ Wh, const __half* __restrict__ Xt,
    const float* __restrict__ bq, const float* __restrict__ bk,
    const float* __restrict__ bv,
    __half* __restrict__ Qh, float* __restrict__ Yk, __half* __restrict__ Kh,
    float* __restrict__ Yv, __half* __restrict__ Vh)
{
    extern __shared__ char smem[];
    const int widx = blockIdx.y >> 5;
    const int m0 = (blockIdx.y & 31) * 128;
    const int n0 = blockIdx.x * 128;
    const size_t boff = (size_t)blockIdx.z * CH * SSZ;
    const __half* A = Wh + (size_t)widx * WSZ;
    const __half* Bb = Xt + (size_t)blockIdx.z * SSZ * CH;
    const float* bias = (widx == 0) ? bq : (widx == 1) ? bk : bv;
    float*  Yf = (widx == 0) ? (float*)0 : (widx == 1) ? Yk + boff : Yv + boff;
    __half* Yh = (widx == 0) ? Qh + boff : (widx == 1) ? Kh + boff : Vh + boff;
    gemm_core_h(A, Bb, bias, Yf, Yh, m0, n0, smem);
}

// Single GEMM (output projection), fp32 out only
__global__ __launch_bounds__(256, 2) void gemm_one(
    const __half* __restrict__ A, const __half* __restrict__ Bt,
    const float* __restrict__ bias, float* __restrict__ Y)
{
    extern __shared__ char smem[];
    const int m0 = blockIdx.y * 128;
    const int n0 = blockIdx.x * 128;
    const __half* Bb = Bt + (size_t)blockIdx.z * SSZ * CH;
    float*        Yb = Y  + (size_t)blockIdx.z * CH * SSZ;
    gemm_core_h(A, Bb, bias, Yb, (__half*)0, m0, n0, smem);
}

// ===========================================================================
// Tensor-core attention, 1 CTA per (b,h), 256 threads.
// SMEM map (192KB):
//   [0, 96K)     phase1: 3 x 32KB stages; phase2: V0 @0, V1 @32K
//   [96K, 160K)  scores fp32 (128x128); phase2: attnT out-stage half (32KB)
//   [160K, 192K) P half (128x128, xor-swizzled 256B rows)
// ===========================================================================
#define ATTN_SMEM 196608
#define OFF_SC 98304
#define OFF_P  163840

__global__ __launch_bounds__(256, 1) void attn_tc(
    const __half* __restrict__ Qh, const __half* __restrict__ Kh,
    const __half* __restrict__ Vh, __half* __restrict__ OT)
{
    extern __shared__ char smem[];
    const uint32_t sb = smem_u32(smem);
    float*  scores = (float*)(smem + OFF_SC);
    __half* Pp     = (__half*)(smem + OFF_P);
    const uint32_t Pb = sb + OFF_P;

    const int bh = blockIdx.x;
    const int b_ = bh >> 5, h_ = bh & 31;
    const size_t hb = ((size_t)b_ * CH + (size_t)h_ * HD) * SSZ;
    const __half* q = Qh + hb;
    const __half* k = Kh + hb;
    const __half* v = Vh + hb;
    __half* oT = OT + (size_t)b_ * SSZ * CH + h_ * HD;

    const int t    = threadIdx.x;
    const int lane = t & 31;
    const int wid  = t >> 5;
    const int wm   = wid >> 2;
    const int wn   = wid & 3;
    const int lr = t >> 3;
    const int lc = t & 7;

    float acc[4][4][4];
#pragma unroll
    for (int mt = 0; mt < 4; mt++)
#pragma unroll
        for (int nt = 0; nt < 4; nt++)
#pragma unroll
            for (int x = 0; x < 4; x++) acc[mt][nt][x] = 0.0f;

    // ---------------- Phase 1: scores = Qh @ Kh^T (K = 2048) ----------------
    auto issue1 = [&](int chunk) {
        const int stage = chunk % 3;
        const int k0 = chunk * 64;
        const uint32_t As = sb + stage * STAGE_H;
        const uint32_t Bs = As + 16384;
#pragma unroll
        for (int it = 0; it < 4; it++) {
            int m = it * 32 + lr;
            uint32_t sw = (uint32_t)(m * 128 + ((lc ^ (m & 7)) << 4));
            cp16(As + sw, q + (size_t)m * SSZ + k0 + lc * 8);
            cp16(Bs + sw, k + (size_t)m * SSZ + k0 + lc * 8);
        }
        CP_COMMIT();
    };
    issue1(0); issue1(1); issue1(2);

    for (int i = 0; i < 32; i++) {
        CP_WAIT(2);
        __syncthreads();
        const uint32_t As = sb + (i % 3) * STAGE_H;
        const uint32_t Bs = As + 16384;
#pragma unroll
        for (int ks = 0; ks < 4; ks++) {
            uint32_t a[4][4], b[2][4];
#pragma unroll
            for (int mt = 0; mt < 4; mt++) {
                int row = wm * 64 + mt * 16 + (lane & 15);
                int ch  = ks * 2 + (lane >> 4);
                ldsm_x4(a[mt][0], a[mt][1], a[mt][2], a[mt][3],
                        As + row * 128 + ((ch ^ (row & 7)) << 4));
            }
#pragma unroll
            for (int p = 0; p < 2; p++) {
                int row = wn * 32 + p * 16 + ((lane >> 4) << 3) + (lane & 7);
                int ch  = ks * 2 + ((lane >> 3) & 1);
                ldsm_x4(b[p][0], b[p][1], b[p][2], b[p][3],
                        Bs + row * 128 + ((ch ^ (row & 7)) << 4));
            }
#pragma unroll
            for (int mt = 0; mt < 4; mt++)
#pragma unroll
                for (int nt = 0; nt < 4; nt++)
                    mma_f16(acc[mt][nt], a[mt], &b[nt >> 1][(nt & 1) * 2]);
        }
        __syncthreads();
        if (i + 3 < 32) issue1(i + 3);
        else CP_COMMIT();
    }
    CP_WAIT(0);

    // scale + causal mask -> scores fp32
    {
        const float scale = rsqrtf((float)SSZ);
        const int r = lane >> 2;
        const int c = lane & 3;
#pragma unroll
        for (int mt = 0; mt < 4; mt++) {
            int row0 = wm * 64 + mt * 16 + r;
            int row1 = row0 + 8;
#pragma unroll
            for (int nt = 0; nt < 4; nt++) {
                int col = wn * 32 + nt * 8 + c * 2;
                scores[row0 * 128 + col]     = (col     <= row0) ? acc[mt][nt][0] * scale : -1e30f;
                scores[row0 * 128 + col + 1] = (col + 1 <= row0) ? acc[mt][nt][1] * scale : -1e30f;
                scores[row1 * 128 + col]     = (col     <= row1) ? acc[mt][nt][2] * scale : -1e30f;
                scores[row1 * 128 + col + 1] = (col + 1 <= row1) ? acc[mt][nt][3] * scale : -1e30f;
            }
        }
    }
    __syncthreads();

    // ---------------- Softmax (warp per 16 rows) -> P half (swizzled) -------
#pragma unroll 4
    for (int rr = 0; rr < 16; rr++) {
        int row = wid * 16 + rr;
        float v0 = scores[row * 128 + lane];
        float v1 = scores[row * 128 + lane + 32];
        float v2 = scores[row * 128 + lane + 64];
        float v3 = scores[row * 128 + lane + 96];
        float mx = fmaxf(fmaxf(v0, v1), fmaxf(v2, v3));
#pragma unroll
        for (int o = 16; o > 0; o >>= 1)
            mx = fmaxf(mx, __shfl_xor_sync(0xFFFFFFFFu, mx, o));
        float e0 = __expf(v0 - mx), e1 = __expf(v1 - mx);
        float e2 = __expf(v2 - mx), e3 = __expf(v3 - mx);
        float sm = e0 + e1 + e2 + e3;
#pragma unroll
        for (int o = 16; o > 0; o >>= 1)
            sm += __shfl_xor_sync(0xFFFFFFFFu, sm, o);
        float inv = 1.0f / sm;
        float ev[4] = {e0, e1, e2, e3};
#pragma unroll
        for (int j = 0; j < 4; j++) {
            int col = lane + 32 * j;
            int hidx = row * 128 + ((((col >> 3) ^ (row & 7))) << 3) + (col & 7);
            Pp[hidx] = __float2half_rn(ev[j] * inv);
        }
    }

    // ---------------- Phase 2: attnT[s][d] = (P @ V)^T, chunked over s -------
    auto issueV = [&](int nc) {
        const uint32_t Vb = sb + (nc & 1) * 32768;
        const int n0 = nc * 128;
#pragma unroll
        for (int i = 0; i < 8; i++) {
            int idx = i * 256 + t;
            int e = idx >> 4;
            int c = idx & 15;
            cp16(Vb + (uint32_t)(e * 256 + ((c ^ (e & 7)) << 4)),
                 v + (size_t)e * SSZ + n0 + c * 8);
        }
        CP_COMMIT();
    };
    issueV(0);

    __half* OTp = (__half*)(smem + OFF_SC);   // reuse scores region

    for (int nc = 0; nc < 16; nc++) {
        if (nc + 1 < 16) { issueV(nc + 1); CP_WAIT(1); }
        else             { CP_WAIT(0); }
        __syncthreads();   // V[nc] visible; P/softmax done (nc==0); OT stage free

        const uint32_t Vb = sb + (nc & 1) * 32768;
#pragma unroll
        for (int mt = 0; mt < 4; mt++)
#pragma unroll
            for (int nt = 0; nt < 4; nt++)
#pragma unroll
                for (int x = 0; x < 4; x++) acc[mt][nt][x] = 0.0f;

#pragma unroll
        for (int ks = 0; ks < 8; ks++) {
            uint32_t a[4][4], b[2][4];
#pragma unroll
            for (int mt = 0; mt < 4; mt++) {
                int row = wm * 64 + mt * 16 + (lane & 15);
                int ch  = ks * 2 + (lane >> 4);
                ldsm_x4(a[mt][0], a[mt][1], a[mt][2], a[mt][3],
                        Pb + row * 256 + ((ch ^ (row & 7)) << 4));
            }
#pragma unroll
            for (int p = 0; p < 2; p++) {
                int nb  = wn * 32 + p * 16;
                int grp = lane >> 3;
                int li  = lane & 7;
                int e   = ks * 16 + ((grp & 1) << 3) + li;
                int ncol = nb + ((grp >> 1) << 3);
                ldsm_x4_t(b[p][0], b[p][1], b[p][2], b[p][3],
                          Vb + e * 256 + (((ncol >> 3) ^ (e & 7)) << 4));
            }
#pragma unroll
            for (int mt = 0; mt < 4; mt++)
#pragma unroll
                for (int nt = 0; nt < 4; nt++)
                    mma_f16(acc[mt][nt], a[mt], &b[nt >> 1][(nt & 1) * 2]);
        }

        // stage attnT tile [s][d] in smem (half)
        {
            const int r = lane >> 2;
            const int c = lane & 3;
#pragma unroll
            for (int mt = 0; mt < 4; mt++) {
                int row0 = wm * 64 + mt * 16 + r;
#pragma unroll
                for (int nt = 0; nt < 4; nt++) {
                    int col = wn * 32 + nt * 8 + c * 2;
                    OTp[col * 128 + row0]           = __float2half_rn(acc[mt][nt][0]);
                    OTp[(col + 1) * 128 + row0]     = __float2half_rn(acc[mt][nt][1]);
                    OTp[col * 128 + row0 + 8]       = __float2half_rn(acc[mt][nt][2]);
                    OTp[(col + 1) * 128 + row0 + 8] = __float2half_rn(acc[mt][nt][3]);
                }
            }
        }
        __syncthreads();

        // coalesced global store: 128 rows x 256B
        {
            int s  = t >> 1;
            int dp = (t & 1) * 64;
            const uint4* src = (const uint4*)(OTp + s * 128 + dp);
            uint4* dst = (uint4*)(oT + (size_t)(nc * 128 + s) * CH + dp);
#pragma unroll
            for (int u = 0; u < 8; u++) dst[u] = src[u];
        }
        __syncthreads();
    }
}

// ===========================================================================
// Launch
// ===========================================================================
extern "C" void kernel_launch(void* const* d_in, const int* in_sizes, int n_in,
                              void* d_out, int out_size)
{
    const float* hs = (const float*)d_in[0];
    const float* Wq = (const float*)d_in[1];
    const float* bq = (const float*)d_in[2];
    const float* Wk = (const float*)d_in[3];
    const float* bk = (const float*)d_in[4];
    const float* Wv = (const float*)d_in[5];
    const float* bv = (const float*)d_in[6];
    const float* Wo = (const float*)d_in[7];
    const float* bo = (const float*)d_in[8];

    float *kfb, *vfb;
    __half *qh, *kh, *vh, *atbufh, *xth, *wh;
    cudaGetSymbolAddress((void**)&qh,     g_qh);
    cudaGetSymbolAddress((void**)&kh,     g_kh);
    cudaGetSymbolAddress((void**)&vh,     g_vh);
    cudaGetSymbolAddress((void**)&atbufh, g_attnTh);
    cudaGetSymbolAddress((void**)&xth,    g_xth);
    cudaGetSymbolAddress((void**)&wh,     g_wh);
    cudaGetSymbolAddress((void**)&kfb,    g_kfb);
    cudaGetSymbolAddress((void**)&vfb,    g_vfb);

    float* out = (float*)d_out;
    float* kout;
    float* vout;
    if ((long long)out_size >= 3LL * BHS) {
        kout = out + (size_t)BHS;
        vout = out + 2 * (size_t)BHS;
    } else {
        kout = kfb;
        vout = vfb;
    }

    // ---- Prep ----
    const int rblocks = WSZ / (256 * 8);
    round_half_kernel<<<rblocks, 256>>>(Wq, wh + 0 * (size_t)WSZ);
    round_half_kernel<<<rblocks, 256>>>(Wk, wh + 1 * (size_t)WSZ);
    round_half_kernel<<<rblocks, 256>>>(Wv, wh + 2 * (size_t)WSZ);
    round_half_kernel<<<rblocks, 256>>>(Wo, wh + 3 * (size_t)WSZ);
    transpose_half_kernel<<<dim3(SSZ / 32, CH / 32, BB), 256>>>(hs, xth);

    // ---- Fused Q/K/V projections ----
    cudaFuncSetAttribute(gemm_qkv,
                         cudaFuncAttributeMaxDynamicSharedMemorySize, SMEM_H);
    cudaFuncSetAttribute(gemm_one,
                         cudaFuncAttributeMaxDynamicSharedMemorySize, SMEM_H);
    dim3 blk(256, 1, 1);
    gemm_qkv<<<dim3(SSZ / 128, 96, BB), blk, SMEM_H>>>(
        wh, xth, bq, bk, bv, qh, kout, kh, vout, vh);

    // ---- Tensor-core attention ----
    cudaFuncSetAttribute(attn_tc,
                         cudaFuncAttributeMaxDynamicSharedMemorySize, ATTN_SMEM);
    attn_tc<<<BB * NH, 256, ATTN_SMEM>>>(qh, kh, vh, atbufh);

    // ---- Output projection ----
    gemm_one<<<dim3(SSZ / 128, CH / 128, BB), blk, SMEM_H>>>(
        wh + 3 * (size_t)WSZ, atbufh, bo, out);
}